// round 5
// baseline (speedup 1.0000x reference)
#include <cuda_runtime.h>
#include <stdint.h>

// Fixed problem shapes
#define NW 30
#define NE 300
#define ROW_BYTES   (NE * 4)           // 1200
#define SENT_BYTES  (NW * ROW_BYTES)   // 36000
#define NSENT 1024
#define EMB_ELEMS (NSENT * NW * NE)    // 9,216,000
#define OFF_SHARE  EMB_ELEMS
#define OFF_MASK   (2 * EMB_ELEMS)
#define OFF_WMASK  (OFF_MASK + NSENT * NW)
#define OFF_SMASK  (OFF_WMASK + NSENT * NW)

__device__ __forceinline__ uint32_t smem_u32(const void* p) {
    return (uint32_t)__cvta_generic_to_shared(p);
}

__device__ __forceinline__ void bulk_g2s(uint32_t dst_smem, const void* src_gmem,
                                         uint32_t bytes, uint32_t mbar) {
    asm volatile(
        "cp.async.bulk.shared::cta.global.mbarrier::complete_tx::bytes [%0], [%1], %2, [%3];"
        :: "r"(dst_smem), "l"(src_gmem), "r"(bytes), "r"(mbar) : "memory");
}

__device__ __forceinline__ void bulk_s2g(void* dst_gmem, uint32_t src_smem, uint32_t bytes) {
    asm volatile(
        "cp.async.bulk.global.shared::cta.bulk_group [%0], [%1], %2;"
        :: "l"(dst_gmem), "r"(src_smem), "r"(bytes) : "memory");
}

__global__ __launch_bounds__(128) void embed_bulk_kernel(
    const int* __restrict__ input_var,   // [1024*30] int32 tokens
    const float* __restrict__ W_emb,     // [50000*300]
    float* __restrict__ out)
{
    __shared__ __align__(16) unsigned char s_rows[SENT_BYTES];  // 30 gathered rows
    __shared__ __align__(16) unsigned char s_row0[ROW_BYTES];   // W_emb[0] (truncation fill)
    __shared__ __align__(8)  unsigned long long s_mbar;
    __shared__ int s_tok[NW];
    __shared__ int s_keep[NW];

    const int sent = blockIdx.x;
    const int tid  = threadIdx.x;
    const uint32_t mbar = smem_u32(&s_mbar);

    if (tid < NW) s_tok[tid] = input_var[sent * NW + tid];
    if (tid == 0) {
        asm volatile("mbarrier.init.shared.b64 [%0], %1;" :: "r"(mbar), "r"(1) : "memory");
    }
    __syncthreads();

    // keep = cumprod of (tok != 0); mask == keep; wmask = tok != 0
    if (tid < NW) {
        bool keep = true;
        #pragma unroll
        for (int k = 0; k <= tid; k++) keep = keep && (s_tok[k] != 0);
        s_keep[tid] = keep ? 1 : 0;
        out[OFF_MASK  + sent * NW + tid] = keep ? 1.0f : 0.0f;
        out[OFF_WMASK + sent * NW + tid] = (s_tok[tid] != 0) ? 1.0f : 0.0f;
    }
    if (tid == 32) {  // different warp: overlap with mask warp
        bool any = false;
        #pragma unroll
        for (int k = 0; k < NW; k++) any = any || (s_tok[k] != 0);
        out[OFF_SMASK + sent] = any ? 1.0f : 0.0f;
    }
    __syncthreads();

    if (tid == 0) {
        // One mbarrier transaction covering all gathers
        asm volatile("mbarrier.arrive.expect_tx.shared.b64 _, [%0], %1;"
                     :: "r"(mbar), "r"(SENT_BYTES + ROW_BYTES) : "memory");

        const char* embb = (const char*)W_emb;
        bulk_g2s(smem_u32(s_row0), embb, ROW_BYTES, mbar);
        const uint32_t rows_base = smem_u32(s_rows);
        #pragma unroll
        for (int w = 0; w < NW; w++) {
            bulk_g2s(rows_base + w * ROW_BYTES,
                     embb + (size_t)s_tok[w] * ROW_BYTES, ROW_BYTES, mbar);
        }

        // Wait (parity 0, single use per launch)
        {
            uint32_t done;
            asm volatile(
                "{\n\t.reg .pred p;\n\t"
                "mbarrier.try_wait.parity.acquire.cta.shared::cta.b64 p, [%1], %2;\n\t"
                "selp.b32 %0, 1, 0, p;\n\t}"
                : "=r"(done) : "r"(mbar), "r"(0) : "memory");
            if (!done) {
                asm volatile(
                    "{\n\t.reg .pred P1;\n\t"
                    "WL_%=:\n\t"
                    "mbarrier.try_wait.parity.acquire.cta.shared::cta.b64 P1, [%0], %1, 0x989680;\n\t"
                    "@P1 bra.uni WD_%=;\n\t"
                    "bra.uni WL_%=;\n\t"
                    "WD_%=:\n\t}"
                    :: "r"(mbar), "r"(0) : "memory");
            }
        }

        // Store embedded: one contiguous 36 KB bulk store
        char* dst_e = (char*)out + (size_t)sent * SENT_BYTES;
        bulk_s2g(dst_e, rows_base, SENT_BYTES);

        // share_enc_embedded: identical unless some row was truncated/zero
        bool allkept = true;
        #pragma unroll
        for (int w = 0; w < NW; w++) allkept = allkept && (s_keep[w] != 0);

        char* dst_s = (char*)(out + OFF_SHARE) + (size_t)sent * SENT_BYTES;
        if (allkept) {
            bulk_s2g(dst_s, rows_base, SENT_BYTES);
        } else {
            const uint32_t row0 = smem_u32(s_row0);
            #pragma unroll
            for (int w = 0; w < NW; w++) {
                bulk_s2g(dst_s + w * ROW_BYTES,
                         s_keep[w] ? (rows_base + w * ROW_BYTES) : row0,
                         ROW_BYTES);
            }
        }

        // Ensure bulk stores have finished READING smem before CTA teardown
        asm volatile("cp.async.bulk.commit_group;" ::: "memory");
        asm volatile("cp.async.bulk.wait_group.read 0;" ::: "memory");
    }
}

extern "C" void kernel_launch(void* const* d_in, const int* in_sizes, int n_in,
                              void* d_out, int out_size) {
    const int*   input_var = (const int*)d_in[0];
    const float* W_emb     = (const float*)d_in[1];
    float*       out       = (float*)d_out;

    embed_bulk_kernel<<<NSENT, 128>>>(input_var, W_emb, out);
}

// round 6
// speedup vs baseline: 1.0111x; 1.0111x over previous
#include <cuda_runtime.h>
#include <stdint.h>

// Fixed problem shapes
#define NW 30
#define NE 300
#define NEV 75                     // float4 per row
#define ROW_B   (NE * 4)           // 1200
#define SENT_V  (NW * NEV)         // 2250 float4
#define SENT_B  (NW * ROW_B)       // 36000
#define NSENT 1024
#define EMB_ELEMS (NSENT * NW * NE)
#define OFF_SHARE  EMB_ELEMS
#define OFF_MASK   (2 * EMB_ELEMS)
#define OFF_WMASK  (OFF_MASK + NSENT * NW)
#define OFF_SMASK  (OFF_WMASK + NSENT * NW)

__device__ __forceinline__ uint32_t smem_u32(const void* p) {
    return (uint32_t)__cvta_generic_to_shared(p);
}

__device__ __forceinline__ void bulk_s2g(void* dst_gmem, uint32_t src_smem, uint32_t bytes) {
    asm volatile(
        "cp.async.bulk.global.shared::cta.bulk_group [%0], [%1], %2;"
        :: "l"(dst_gmem), "r"(src_smem), "r"(bytes) : "memory");
}

__global__ __launch_bounds__(256) void embed_hybrid_kernel(
    const int* __restrict__ input_var,   // [1024*30] int32 tokens
    const float* __restrict__ W_emb,     // [50000*300]
    float* __restrict__ out)
{
    __shared__ __align__(16) float4 s_sent[SENT_V];  // 36000 B staged sentence
    __shared__ __align__(16) float4 s_row0[NEV];     // 1200 B: W_emb[0] (truncation fill)
    __shared__ int s_tok[NW];
    __shared__ int s_keep[NW];

    const int sent = blockIdx.x;
    const int tid  = threadIdx.x;

    if (tid < NW) s_tok[tid] = input_var[sent * NW + tid];
    __syncthreads();

    // Masks (warp 0) — runs concurrently with the gather loop below
    if (tid < NW) {
        bool keep = true;
        #pragma unroll
        for (int k = 0; k <= tid; k++) keep = keep && (s_tok[k] != 0);
        s_keep[tid] = keep ? 1 : 0;
        out[OFF_MASK  + sent * NW + tid] = keep ? 1.0f : 0.0f;
        out[OFF_WMASK + sent * NW + tid] = (s_tok[tid] != 0) ? 1.0f : 0.0f;
    }
    if (tid == 32) {
        bool any = false;
        #pragma unroll
        for (int k = 0; k < NW; k++) any = any || (s_tok[k] != 0);
        out[OFF_SMASK + sent] = any ? 1.0f : 0.0f;
    }

    // Parallel per-lane gather into SMEM (high MLP; ptxas front-batches loads)
    const float4* __restrict__ emb4 = (const float4*)W_emb;
    #pragma unroll
    for (int i = 0; i < 9; i++) {
        const int v = tid + i * 256;
        if (v < SENT_V) {
            const int w = v / NEV;
            const int j = v - w * NEV;
            s_sent[v] = emb4[(size_t)s_tok[w] * NEV + j];
        }
    }
    if (tid < NEV) s_row0[tid] = emb4[tid];   // fill row for truncated tokens
    __syncthreads();

    // Bulk stores: one 36 KB copy per region (LSU-issue cost ~0)
    if (tid == 0) {
        asm volatile("fence.proxy.async.shared::cta;" ::: "memory");

        float4* dst_e = (float4*)out + (size_t)sent * SENT_V;
        float4* dst_s = (float4*)(out + OFF_SHARE) + (size_t)sent * SENT_V;

        bulk_s2g(dst_e, smem_u32(s_sent), SENT_B);

        bool allkept = true;
        #pragma unroll
        for (int w = 0; w < NW; w++) allkept = allkept && (s_keep[w] != 0);

        if (allkept) {
            bulk_s2g(dst_s, smem_u32(s_sent), SENT_B);
        } else {
            const uint32_t rows = smem_u32(s_sent);
            const uint32_t row0 = smem_u32(s_row0);
            #pragma unroll
            for (int w = 0; w < NW; w++) {
                bulk_s2g(dst_s + w * NEV,
                         s_keep[w] ? (rows + w * ROW_B) : row0, ROW_B);
            }
        }

        // Block CTA retire only until bulk engine finished READING smem
        asm volatile("cp.async.bulk.commit_group;" ::: "memory");
        asm volatile("cp.async.bulk.wait_group.read 0;" ::: "memory");
    }
}

extern "C" void kernel_launch(void* const* d_in, const int* in_sizes, int n_in,
                              void* d_out, int out_size) {
    const int*   input_var = (const int*)d_in[0];
    const float* W_emb     = (const float*)d_in[1];
    float*       out       = (float*)d_out;

    embed_hybrid_kernel<<<NSENT, 256>>>(input_var, W_emb, out);
}

// round 7
// speedup vs baseline: 1.2097x; 1.1963x over previous
#include <cuda_runtime.h>
#include <stdint.h>

// Fixed problem shapes
#define NW 30
#define NE 300
#define NEV 75                   // float4 per embedding row
#define NSENT 1024
#define EMB_ELEMS (NSENT * NW * NE)          // 9,216,000
#define OFF_SHARE  EMB_ELEMS
#define OFF_MASK   (2 * EMB_ELEMS)
#define OFF_WMASK  (OFF_MASK + NSENT * NW)
#define OFF_SMASK  (OFF_WMASK + NSENT * NW)

#define HALF_ROWS 15
#define HALF_VEC  (HALF_ROWS * NEV)          // 1125 float4 per half-sentence
#define BLOCK     256
#define NITER     5                          // ceil(1125/256)

__global__ __launch_bounds__(BLOCK) void embed_fused_kernel(
    const int* __restrict__ input_var,        // [1024*30] int32 tokens
    const float* __restrict__ W_emb,          // [50000*300]
    float* __restrict__ out)
{
    const int sent = blockIdx.x >> 1;   // 0..1023
    const int half = blockIdx.x & 1;    // 0: rows 0-14, 1: rows 15-29
    const int tid  = threadIdx.x;

    __shared__ int s_tok[NW];
    __shared__ int s_keep[NW];

    if (tid < NW) s_tok[tid] = input_var[sent * NW + tid];
    __syncthreads();

    if (tid < NW) {
        bool keep = true;
        #pragma unroll
        for (int k = 0; k <= tid; k++) keep = keep && (s_tok[k] != 0);
        s_keep[tid] = keep ? 1 : 0;
        if (half == 0) {
            out[OFF_MASK  + sent * NW + tid] = keep ? 1.0f : 0.0f;
            out[OFF_WMASK + sent * NW + tid] = (s_tok[tid] != 0) ? 1.0f : 0.0f;
        }
    }
    if (half == 0 && tid == 32) {
        bool any = false;
        #pragma unroll
        for (int k = 0; k < NW; k++) any = any || (s_tok[k] != 0);
        out[OFF_SMASK + sent] = any ? 1.0f : 0.0f;
    }
    __syncthreads();

    const float4* __restrict__ emb4 = (const float4*)W_emb;
    float4* __restrict__ out_e = (float4*)out
        + (size_t)sent * (NW * NEV) + half * HALF_VEC;
    float4* __restrict__ out_s = (float4*)(out + OFF_SHARE)
        + (size_t)sent * (NW * NEV) + half * HALF_VEC;

    // Strength-reduced (w, j) walk: stride 256 = 3*75 + 31
    const int w0 = tid / NEV;          // 0..3 (one division, prologue only)
    const int j0 = tid - w0 * NEV;
    const int rbase = half * HALF_ROWS;

    // Phase 1: 5 fully independent batched gathers (max MLP)
    float4 vals[NITER];
    int    wl[NITER];
    int    jl[NITER];
    {
        int w = w0, j = j0;
        #pragma unroll
        for (int i = 0; i < NITER; i++) {
            wl[i] = w; jl[i] = j;
            if (w < HALF_ROWS) {
                vals[i] = emb4[(size_t)s_tok[rbase + w] * NEV + j];
            }
            j += 31; w += 3;
            if (j >= NEV) { j -= NEV; w += 1; }
        }
    }

    // Phase 2: streaming stores; rare truncated-token substitute = row 0
    #pragma unroll
    for (int i = 0; i < NITER; i++) {
        const int w = wl[i];
        if (w < HALF_ROWS) {
            const int v = w * NEV + jl[i];
            __stcs(&out_e[v], vals[i]);
            float4 x = vals[i];
            if (!s_keep[rbase + w]) x = emb4[jl[i]];   // rare: row 0
            __stcs(&out_s[v], x);
        }
    }
}

extern "C" void kernel_launch(void* const* d_in, const int* in_sizes, int n_in,
                              void* d_out, int out_size) {
    const int*   input_var = (const int*)d_in[0];
    const float* W_emb     = (const float*)d_in[1];
    float*       out       = (float*)d_out;

    embed_fused_kernel<<<2 * NSENT, BLOCK>>>(input_var, W_emb, out);
}

// round 8
// speedup vs baseline: 1.3769x; 1.1383x over previous
#include <cuda_runtime.h>
#include <stdint.h>

// Fixed problem shapes
#define NB 32
#define NS 32
#define NW 30
#define NE 300
#define NEV 75                   // float4 per embedding row (300 floats)
#define NSENT (NB * NS)          // 1024
#define EMB_ELEMS (NSENT * NW * NE)          // 9,216,000
#define OFF_SHARE  EMB_ELEMS
#define OFF_MASK   (2 * EMB_ELEMS)           // 18,432,000
#define OFF_WMASK  (OFF_MASK + NSENT * NW)
#define OFF_SMASK  (OFF_WMASK + NSENT * NW)

#define HALF_ROWS 15
#define HALF_VEC  (HALF_ROWS * NEV)          // 1125 float4 per half-sentence
#define BLOCK     256
#define NITER     5                          // ceil(1125/256)

__global__ __launch_bounds__(BLOCK, 8) void embed_fused_kernel(
    const int* __restrict__ input_var,        // [1024*30] int32 tokens
    const float* __restrict__ W_emb,          // [50000*300]
    float* __restrict__ out)
{
    const int sent = blockIdx.x >> 1;   // 0..1023
    const int half = blockIdx.x & 1;    // 0: rows 0-14, 1: rows 15-29
    const int tid  = threadIdx.x;

    __shared__ int s_tok[NW];
    __shared__ unsigned s_kmask;        // bit w set => token w kept (before first zero)

    // Warp 0: load tokens + compute all masks with one ballot
    if (tid < 32) {
        const int t = (tid < NW) ? input_var[sent * NW + tid] : 1;
        if (tid < NW) s_tok[tid] = t;
        const unsigned nz = __ballot_sync(0xFFFFFFFFu, t != 0);  // bit per lane: tok!=0
        // keep = lanes strictly below the first zero lane:
        const unsigned firstzero = ~nz;                     // lowest set bit = first zero
        const unsigned keepmask  = (firstzero - 1u) & ~firstzero & 0x3FFFFFFFu;
        if (tid == 0) s_kmask = keepmask;
        if (half == 0 && tid < NW) {
            out[OFF_MASK  + sent * NW + tid] = (keepmask >> tid & 1u) ? 1.0f : 0.0f;
            out[OFF_WMASK + sent * NW + tid] = (t != 0) ? 1.0f : 0.0f;
        }
        if (half == 0 && tid == 0) {
            out[OFF_SMASK + sent] = ((nz & 0x3FFFFFFFu) != 0u) ? 1.0f : 0.0f;
        }
    }
    __syncthreads();

    const unsigned kmask = s_kmask;
    const float4* __restrict__ emb4 = (const float4*)W_emb;
    float4* __restrict__ out_e = (float4*)out
        + (size_t)sent * (NW * NEV) + half * HALF_VEC;
    float4* __restrict__ out_s = (float4*)(out + OFF_SHARE)
        + (size_t)sent * (NW * NEV) + half * HALF_VEC;
    const int rbase = half * HALF_ROWS;

    // Phase 1: 5 fully independent batched gathers (max MLP)
    float4 vals[NITER];
    #pragma unroll
    for (int i = 0; i < NITER; i++) {
        const int v = tid + i * BLOCK;
        if (v < HALF_VEC) {
            const int w = v / NEV;          // mul-shift
            const int j = v - w * NEV;
            vals[i] = emb4[(size_t)s_tok[rbase + w] * NEV + j];
        }
    }

    // Phase 2: streaming stores; rare truncated token -> row 0 (predicated reload)
    #pragma unroll
    for (int i = 0; i < NITER; i++) {
        const int v = tid + i * BLOCK;
        if (v < HALF_VEC) {
            const int w = v / NEV;
            const int j = v - w * NEV;
            __stcs(&out_e[v], vals[i]);
            float4 x = vals[i];
            if (!(kmask >> (rbase + w) & 1u)) x = emb4[j];   // row 0
            __stcs(&out_s[v], x);
        }
    }
}

extern "C" void kernel_launch(void* const* d_in, const int* in_sizes, int n_in,
                              void* d_out, int out_size) {
    const int*   input_var = (const int*)d_in[0];
    const float* W_emb     = (const float*)d_in[1];
    float*       out       = (float*)d_out;

    embed_fused_kernel<<<2 * NSENT, BLOCK>>>(input_var, W_emb, out);
}